// round 3
// baseline (speedup 1.0000x reference)
#include <cuda_runtime.h>
#include <math.h>

#define SEQ   2097152
#define CHUNK 1024            // number of chunks == threads in fixpoint block
#define LOG2C 10
#define LSTEP (SEQ / CHUNK)   // 2048 steps per chunk

// ---------------- scratch (static device globals; no allocation) ------------
__device__ float2 g_c[SEQ];       // c_t, chunk-transposed: index = s*CHUNK + k
__device__ float2 g_yin[CHUNK];   // converged entry state per chunk
__device__ float  g_M[8];         // folded input matrix M[h][i] (2x4)
__device__ float  g_d[2];         // folded bias
__device__ float  g_B[4];         // recurrence matrix B[h][j] (2x2)
__device__ float  g_W2[4];        // output matrix (2x2, row-major)
__device__ float  g_b2[2];

// ---------------- K0: fold weights (tiny) -----------------------------------
__global__ void k0_fold(const float* __restrict__ W1, const float* __restrict__ b1,
                        const float* __restrict__ Wd, const float* __restrict__ bd,
                        const float* __restrict__ W2, const float* __restrict__ b2) {
    // z = [h_t ; y] -> Wd cols 0..1 act on h_t (A), cols 2..3 act on y (B)
    #pragma unroll
    for (int h = 0; h < 2; ++h) {
        float a0 = Wd[h * 4 + 0];
        float a1 = Wd[h * 4 + 1];
        #pragma unroll
        for (int i = 0; i < 4; ++i)
            g_M[h * 4 + i] = a0 * W1[0 * 4 + i] + a1 * W1[1 * 4 + i];
        g_d[h] = a0 * b1[0] + a1 * b1[1] + bd[h];
        g_B[h * 2 + 0] = Wd[h * 4 + 2];
        g_B[h * 2 + 1] = Wd[h * 4 + 3];
    }
    #pragma unroll
    for (int i = 0; i < 4; ++i) g_W2[i] = W2[i];
    g_b2[0] = b2[0];
    g_b2[1] = b2[1];
}

// ---------------- K1: c_t = M x_t + d, chunk-transposed store ---------------
__global__ void k1_precompute(const float4* __restrict__ x) {
    int u = blockIdx.x * blockDim.x + threadIdx.x;  // u = s*CHUNK + k
    if (u >= SEQ) return;
    int k = u & (CHUNK - 1);
    int s = u >> LOG2C;
    int t = k * LSTEP + s;
    float4 xv = __ldg(&x[t]);
    float m0 = g_M[0], m1 = g_M[1], m2 = g_M[2], m3 = g_M[3];
    float m4 = g_M[4], m5 = g_M[5], m6 = g_M[6], m7 = g_M[7];
    float c0 = fmaf(m0, xv.x, fmaf(m1, xv.y, fmaf(m2, xv.z, fmaf(m3, xv.w, g_d[0]))));
    float c1 = fmaf(m4, xv.x, fmaf(m5, xv.y, fmaf(m6, xv.z, fmaf(m7, xv.w, g_d[1]))));
    g_c[u] = make_float2(c0, c1);
}

// ---------------- K2: Jacobi fixpoint over chunk boundaries -----------------
__global__ void __launch_bounds__(CHUNK) k2_fixpoint() {
    __shared__ float2 bnd[CHUNK + 1];
    const int tid = threadIdx.x;

    bnd[tid] = make_float2(0.f, 0.f);
    if (tid == 0) bnd[CHUNK] = make_float2(0.f, 0.f);

    const float B00 = g_B[0], B01 = g_B[1], B10 = g_B[2], B11 = g_B[3];

    float2 cached = make_float2(0.f, 0.f);
    unsigned prev0 = 0xFFFFFFFFu, prev1 = 0xFFFFFFFFu;  // sentinel: force 1st compute

    __syncthreads();

    for (int iter = 0; iter < CHUNK + 2; ++iter) {
        float2 yin = bnd[tid];
        float2 old = bnd[tid + 1];
        unsigned yi0 = __float_as_uint(yin.x);
        unsigned yi1 = __float_as_uint(yin.y);

        if (yi0 != prev0 || yi1 != prev1) {
            prev0 = yi0; prev1 = yi1;
            float y0 = yin.x, y1 = yin.y;
            const float2* cp = g_c + tid;
            #pragma unroll 8
            for (int s = 0; s < LSTEP; ++s) {
                float2 c = cp[(size_t)s * CHUNK];
                float n0 = fmaxf(fmaf(B01, y1, fmaf(B00, y0, c.x)), 0.f);
                float n1 = fmaxf(fmaf(B11, y1, fmaf(B10, y0, c.y)), 0.f);
                y0 = n0; y1 = n1;
            }
            cached = make_float2(y0, y1);
        }

        __syncthreads();                 // all reads of bnd done
        bnd[tid + 1] = cached;           // each slot written by exactly one thread
        int changed = (__float_as_uint(cached.x) != __float_as_uint(old.x)) |
                      (__float_as_uint(cached.y) != __float_as_uint(old.y));
        if (__syncthreads_or(changed) == 0) break;   // barrier + convergence test
    }

    g_yin[tid] = bnd[tid];   // converged entry state for each chunk
}

// ---------------- K3: replay chunks from exact entry, fused output ----------
__global__ void k3_output(float2* __restrict__ out) {
    const int k = blockIdx.x;
    if (threadIdx.x != 0) return;

    const float B00 = g_B[0], B01 = g_B[1], B10 = g_B[2], B11 = g_B[3];
    const float W20 = g_W2[0], W21 = g_W2[1], W22 = g_W2[2], W23 = g_W2[3];
    const float bo0 = g_b2[0], bo1 = g_b2[1];

    float2 yin = g_yin[k];
    float y0 = yin.x, y1 = yin.y;
    const float2* cp = g_c + k;
    float2* op = out + (size_t)k * LSTEP;

    #pragma unroll 4
    for (int s = 0; s < LSTEP; ++s) {
        float2 c = cp[(size_t)s * CHUNK];
        float n0 = fmaxf(fmaf(B01, y1, fmaf(B00, y0, c.x)), 0.f);
        float n1 = fmaxf(fmaf(B11, y1, fmaf(B10, y0, c.y)), 0.f);
        y0 = n0; y1 = n1;
        float z0 = fmaf(W20, y0, fmaf(W21, y1, bo0));
        float z1 = fmaf(W22, y0, fmaf(W23, y1, bo1));
        float o0 = 1.0f / (1.0f + __expf(-z0));
        float o1 = 1.0f / (1.0f + __expf(-z1));
        op[s] = make_float2(o0, o1);
    }
}

// ---------------- launch -----------------------------------------------------
extern "C" void kernel_launch(void* const* d_in, const int* in_sizes, int n_in,
                              void* d_out, int out_size) {
    const float* x  = (const float*)d_in[0];
    const float* W1 = (const float*)d_in[1];
    const float* b1 = (const float*)d_in[2];
    const float* Wd = (const float*)d_in[3];
    const float* bd = (const float*)d_in[4];
    const float* W2 = (const float*)d_in[5];
    const float* b2 = (const float*)d_in[6];
    (void)in_sizes; (void)n_in; (void)out_size;

    k0_fold<<<1, 1>>>(W1, b1, Wd, bd, W2, b2);
    k1_precompute<<<SEQ / 256, 256>>>((const float4*)x);
    k2_fixpoint<<<1, CHUNK>>>();
    k3_output<<<CHUNK, 32>>>((float2*)d_out);
}

// round 4
// speedup vs baseline: 18.9247x; 18.9247x over previous
#include <cuda_runtime.h>
#include <math.h>

#define SEQ   2097152
#define C     8192            // number of chunks
#define L     256             // steps per chunk (C*L == SEQ)
#define KPB   16              // chunks per block in tiled kernels
#define TPB   256             // threads per tiled block
#define NSUP  1024            // fixpoint super-threads
#define SUBS  (C / NSUP)      // 8 chunks per super-thread

// ---------------- scratch (static device globals; no allocation) ------------
__device__ float2 g_c[SEQ];      // c_t, chunk-transposed: index = s*C + k
__device__ float2 g_y[SEQ];      // y_t trajectory, same transposed layout
__device__ float2 g_exit[C];     // exit state of each chunk
__device__ float  g_M[8];        // folded input matrix M[h][i] (2x4)
__device__ float  g_d[2];        // folded bias
__device__ float  g_B[4];        // recurrence matrix B[h][j] (2x2)
__device__ float  g_W2[4];       // output matrix (2x2, row-major)
__device__ float  g_b2[2];

// ---------------- K0: fold weights (tiny) -----------------------------------
__global__ void k0_fold(const float* __restrict__ W1, const float* __restrict__ b1,
                        const float* __restrict__ Wd, const float* __restrict__ bd,
                        const float* __restrict__ W2, const float* __restrict__ b2) {
    #pragma unroll
    for (int h = 0; h < 2; ++h) {
        float a0 = Wd[h * 4 + 0];
        float a1 = Wd[h * 4 + 1];
        #pragma unroll
        for (int i = 0; i < 4; ++i)
            g_M[h * 4 + i] = a0 * W1[0 * 4 + i] + a1 * W1[1 * 4 + i];
        g_d[h] = a0 * b1[0] + a1 * b1[1] + bd[h];
        g_B[h * 2 + 0] = Wd[h * 4 + 2];
        g_B[h * 2 + 1] = Wd[h * 4 + 3];
    }
    #pragma unroll
    for (int i = 0; i < 4; ++i) g_W2[i] = W2[i];
    g_b2[0] = b2[0];
    g_b2[1] = b2[1];
}

// ---------------- K1: fused c precompute + pass-A scan ----------------------
// Block handles 16 complete chunks (k0..k0+15), i.e. 4096 consecutive timesteps.
// Phase 1: coalesced x reads -> c -> smem tile [s][kk] (padded)
// Phase 1.5: coalesced g_c writes from tile
// Phase 2: 16 threads scan their chunk from y=0, overwriting tile with y
// Phase 3: coalesced g_y writes from tile
__global__ void __launch_bounds__(TPB) k1_scan(const float4* __restrict__ x) {
    __shared__ float2 tile[L * 17];          // [s*17 + kk], pad avoids conflicts
    const int tid = threadIdx.x;
    const int k0  = blockIdx.x * KPB;
    const size_t tbase = (size_t)k0 * L;

    const float m0 = g_M[0], m1 = g_M[1], m2 = g_M[2], m3 = g_M[3];
    const float m4 = g_M[4], m5 = g_M[5], m6 = g_M[6], m7 = g_M[7];
    const float d0 = g_d[0], d1 = g_d[1];

    #pragma unroll
    for (int r = 0; r < 16; ++r) {
        int i = r * TPB + tid;               // i = kk*256 + s
        float4 xv = x[tbase + i];
        int kk = i >> 8, s = i & 255;
        float c0 = fmaf(m0, xv.x, fmaf(m1, xv.y, fmaf(m2, xv.z, fmaf(m3, xv.w, d0))));
        float c1 = fmaf(m4, xv.x, fmaf(m5, xv.y, fmaf(m6, xv.z, fmaf(m7, xv.w, d1))));
        tile[s * 17 + kk] = make_float2(c0, c1);
    }
    __syncthreads();

    #pragma unroll
    for (int r = 0; r < 16; ++r) {
        int j = r * TPB + tid;               // j = s*16 + kk
        int s = j >> 4, kk = j & 15;
        g_c[(size_t)s * C + k0 + kk] = tile[s * 17 + kk];
    }
    __syncthreads();

    if (tid < KPB) {
        const float B00 = g_B[0], B01 = g_B[1], B10 = g_B[2], B11 = g_B[3];
        float y0 = 0.f, y1 = 0.f;
        for (int s = 0; s < L; ++s) {
            float2 c = tile[s * 17 + tid];
            float n0 = fmaxf(fmaf(B01, y1, fmaf(B00, y0, c.x)), 0.f);
            float n1 = fmaxf(fmaf(B11, y1, fmaf(B10, y0, c.y)), 0.f);
            y0 = n0; y1 = n1;
            tile[s * 17 + tid] = make_float2(y0, y1);
        }
        g_exit[k0 + tid] = make_float2(y0, y1);
    }
    __syncthreads();

    #pragma unroll
    for (int r = 0; r < 16; ++r) {
        int j = r * TPB + tid;
        int s = j >> 4, kk = j & 15;
        g_y[(size_t)s * C + k0 + kk] = tile[s * 17 + kk];
    }
}

// ---------------- K2: boundary fixpoint with trajectory-merge early exit ----
// One block of 1024 threads; thread T owns chunks 8T..8T+7 (processed serially).
// Entries seeded from pass-A exits. Each chunk walk stops as soon as the
// recomputed state bitwise-equals the stored trajectory (merged => suffix and
// exit already exact for this entry). Worst case (no merges) degrades to a
// full recompute — never incorrect.
__global__ void __launch_bounds__(NSUP) k2_fixpoint() {
    __shared__ float2 bnd[NSUP + 1];
    const int T = threadIdx.x;
    const float B00 = g_B[0], B01 = g_B[1], B10 = g_B[2], B11 = g_B[3];

    bnd[T] = (T == 0) ? make_float2(0.f, 0.f) : g_exit[T * SUBS - 1];
    if (T == 0) bnd[NSUP] = g_exit[C - 1];

    unsigned prev0 = 0xFFFFFFFFu, prev1 = 0xFFFFFFFFu;  // force first compute
    float2 cached = make_float2(0.f, 0.f);
    __syncthreads();

    for (int iter = 0; iter < NSUP + 2; ++iter) {
        float2 yin = bnd[T];
        float2 old = bnd[T + 1];
        unsigned a0 = __float_as_uint(yin.x);
        unsigned a1 = __float_as_uint(yin.y);

        if (a0 != prev0 || a1 != prev1) {
            prev0 = a0; prev1 = a1;
            float y0 = yin.x, y1 = yin.y;
            for (int j = 0; j < SUBS; ++j) {
                int k = T * SUBS + j;
                int s = 0;
                for (; s < L; ++s) {
                    float2 c = g_c[(size_t)s * C + k];
                    float n0 = fmaxf(fmaf(B01, y1, fmaf(B00, y0, c.x)), 0.f);
                    float n1 = fmaxf(fmaf(B11, y1, fmaf(B10, y0, c.y)), 0.f);
                    y0 = n0; y1 = n1;
                    float2 st = g_y[(size_t)s * C + k];
                    if (__float_as_uint(st.x) == __float_as_uint(y0) &&
                        __float_as_uint(st.y) == __float_as_uint(y1)) {
                        // merged: stored suffix + exit are exact for this entry
                        float2 e = g_exit[k];
                        y0 = e.x; y1 = e.y;
                        break;
                    }
                    g_y[(size_t)s * C + k] = make_float2(y0, y1);
                }
                if (s == L) g_exit[k] = make_float2(y0, y1);
            }
            cached = make_float2(y0, y1);
        }

        __syncthreads();                     // reads of bnd done
        bnd[T + 1] = cached;                 // unique writer per slot
        int changed = (__float_as_uint(cached.x) != __float_as_uint(old.x)) |
                      (__float_as_uint(cached.y) != __float_as_uint(old.y));
        if (__syncthreads_or(changed) == 0) break;
    }
}

// ---------------- K3: sigmoid epilogue with tile transpose ------------------
__global__ void __launch_bounds__(TPB) k3_output(float2* __restrict__ out) {
    __shared__ float2 tile[L * 17];
    const int tid = threadIdx.x;
    const int k0  = blockIdx.x * KPB;
    const float W20 = g_W2[0], W21 = g_W2[1], W22 = g_W2[2], W23 = g_W2[3];
    const float bo0 = g_b2[0], bo1 = g_b2[1];

    #pragma unroll
    for (int r = 0; r < 16; ++r) {
        int j = r * TPB + tid;               // j = s*16 + kk
        int s = j >> 4, kk = j & 15;
        float2 y = g_y[(size_t)s * C + k0 + kk];
        float z0 = fmaf(W20, y.x, fmaf(W21, y.y, bo0));
        float z1 = fmaf(W22, y.x, fmaf(W23, y.y, bo1));
        tile[s * 17 + kk] = make_float2(1.0f / (1.0f + __expf(-z0)),
                                        1.0f / (1.0f + __expf(-z1)));
    }
    __syncthreads();

    #pragma unroll
    for (int r = 0; r < 16; ++r) {
        int i = r * TPB + tid;               // i = kk*256 + s
        int kk = i >> 8, s = i & 255;
        out[(size_t)(k0 + kk) * L + s] = tile[s * 17 + kk];
    }
}

// ---------------- launch -----------------------------------------------------
extern "C" void kernel_launch(void* const* d_in, const int* in_sizes, int n_in,
                              void* d_out, int out_size) {
    const float* x  = (const float*)d_in[0];
    const float* W1 = (const float*)d_in[1];
    const float* b1 = (const float*)d_in[2];
    const float* Wd = (const float*)d_in[3];
    const float* bd = (const float*)d_in[4];
    const float* W2 = (const float*)d_in[5];
    const float* b2 = (const float*)d_in[6];
    (void)in_sizes; (void)n_in; (void)out_size;

    k0_fold<<<1, 1>>>(W1, b1, Wd, bd, W2, b2);
    k1_scan<<<C / KPB, TPB>>>((const float4*)x);
    k2_fixpoint<<<1, NSUP>>>();
    k3_output<<<C / KPB, TPB>>>((float2*)d_out);
}